// round 15
// baseline (speedup 1.0000x reference)
#include <cuda_runtime.h>
#include <cuda_bf16.h>
#include <cstdint>

// Problem dims (fixed by the dataset)
#define BB    4
#define TT    2048
#define EE    1024
#define HH    16
#define DD    64
#define KTOP  3
#define MROWS (BB * TT)      // 8192
#define QKVN  (3 * EE)       // 3072

typedef unsigned long long ull;

// ---------------- scratch (allocation-free rule: __device__ globals) ---------
__device__ float g_qkv[(size_t)MROWS * QKVN];           // 96 MB fp32
__device__ float g_y[(size_t)MROWS * EE];               // 32 MB fp32
__device__ __nv_bfloat16 g_xhi[(size_t)MROWS * EE];
__device__ __nv_bfloat16 g_xlo[(size_t)MROWS * EE];
__device__ __nv_bfloat16 g_wahi[(size_t)QKVN * EE];     // W_attn^T [3072,1024]
__device__ __nv_bfloat16 g_walo[(size_t)QKVN * EE];
__device__ __nv_bfloat16 g_wphi[(size_t)EE * EE];       // W_proj^T [1024,1024]
__device__ __nv_bfloat16 g_wplo[(size_t)EE * EE];
__device__ __nv_bfloat16 g_chi[(size_t)MROWS * EE];     // combined hi/lo
__device__ __nv_bfloat16 g_clo[(size_t)MROWS * EE];

// ---------------- helpers ----------------
__device__ __forceinline__ uint32_t smem_u32(const void* p) {
    uint32_t a;
    asm("{ .reg .u64 t; cvta.to.shared.u64 t, %1; cvt.u32.u64 %0, t; }"
        : "=r"(a) : "l"(p));
    return a;
}
__device__ __forceinline__ void ldsm_x4(uint32_t* r, uint32_t addr) {
    asm volatile("ldmatrix.sync.aligned.m8n8.x4.shared.b16 {%0,%1,%2,%3}, [%4];"
                 : "=r"(r[0]), "=r"(r[1]), "=r"(r[2]), "=r"(r[3]) : "r"(addr));
}
__device__ __forceinline__ void mma16816(float* d, const uint32_t* a,
                                         const uint32_t* b) {
    asm volatile("mma.sync.aligned.m16n8k16.row.col.f32.bf16.bf16.f32 "
                 "{%0,%1,%2,%3}, {%4,%5,%6,%7}, {%8,%9}, {%0,%1,%2,%3};"
                 : "+f"(d[0]), "+f"(d[1]), "+f"(d[2]), "+f"(d[3])
                 : "r"(a[0]), "r"(a[1]), "r"(a[2]), "r"(a[3]),
                   "r"(b[0]), "r"(b[1]));
}

// ---------------- packed f32x2 helpers (Blackwell FFMA2) ----------------
__device__ __forceinline__ ull pk2(float x, float y) {
    ull r; asm("mov.b64 %0, {%1, %2};" : "=l"(r) : "f"(x), "f"(y)); return r;
}
__device__ __forceinline__ void upk2(ull v, float &x, float &y) {
    asm("mov.b64 {%0, %1}, %2;" : "=f"(x), "=f"(y) : "l"(v));
}
__device__ __forceinline__ ull ffma2(ull a, ull b, ull c) {
    ull d; asm("fma.rn.f32x2 %0, %1, %2, %3;" : "=l"(d) : "l"(a), "l"(b), "l"(c)); return d;
}
__device__ __forceinline__ ull fmul2(ull a, ull b) {
    ull d; asm("mul.rn.f32x2 %0, %1, %2;" : "=l"(d) : "l"(a), "l"(b)); return d;
}

// ============ pre-kernels: split-convert and transpose-split ============
__global__ void convert_split_kernel(const float4* __restrict__ src,
                                     __nv_bfloat16* __restrict__ hi,
                                     __nv_bfloat16* __restrict__ lo, int n4) {
    int i = blockIdx.x * blockDim.x + threadIdx.x;
    if (i >= n4) return;
    float4 v = src[i];
    __nv_bfloat16 h0 = __float2bfloat16(v.x), h1 = __float2bfloat16(v.y);
    __nv_bfloat16 h2 = __float2bfloat16(v.z), h3 = __float2bfloat16(v.w);
    __nv_bfloat162* H = (__nv_bfloat162*)(hi + (size_t)i * 4);
    H[0] = __halves2bfloat162(h0, h1);
    H[1] = __halves2bfloat162(h2, h3);
    __nv_bfloat162* L = (__nv_bfloat162*)(lo + (size_t)i * 4);
    L[0] = __halves2bfloat162(__float2bfloat16(v.x - __bfloat162float(h0)),
                              __float2bfloat16(v.y - __bfloat162float(h1)));
    L[1] = __halves2bfloat162(__float2bfloat16(v.z - __bfloat162float(h2)),
                              __float2bfloat16(v.w - __bfloat162float(h3)));
}

// W [K,N] row-major -> Wt [N,K] split into bf16 hi/lo
__global__ void transpose_split_kernel(const float* __restrict__ W,
                                       __nv_bfloat16* __restrict__ Thi,
                                       __nv_bfloat16* __restrict__ Tlo,
                                       int K, int N) {
    __shared__ float t[32][33];
    int n0 = blockIdx.x * 32, k0 = blockIdx.y * 32;
    int tx = threadIdx.x, ty = threadIdx.y;
    #pragma unroll
    for (int r = 0; r < 32; r += 8)
        t[ty + r][tx] = W[(size_t)(k0 + ty + r) * N + n0 + tx];
    __syncthreads();
    #pragma unroll
    for (int r = 0; r < 32; r += 8) {
        float v = t[tx][ty + r];
        __nv_bfloat16 h = __float2bfloat16(v);
        size_t o = (size_t)(n0 + ty + r) * K + k0 + tx;
        Thi[o] = h;
        Tlo[o] = __float2bfloat16(v - __bfloat162float(h));
    }
}

// ============ mma.sync split-bf16 GEMM ============
// C[M,N] = A[M,K] @ Bt[N,K]^T, fp32 out. BM=BN=128, BK=32, 256 thr, 8 warps.
// Warp grid 4(m) x 2(n); warp tile 32x64; m16n8k16 HMMA; pad-80B smem rows.
#define GS_STRIDE 80
#define GS_AHI 0
#define GS_ALO (128 * GS_STRIDE)
#define GS_BHI (2 * 128 * GS_STRIDE)
#define GS_BLO (3 * 128 * GS_STRIDE)
#define GS_TOTAL (4 * 128 * GS_STRIDE)   // 40960 B

__global__ __launch_bounds__(256, 2)
void gemm_mma_kernel(const __nv_bfloat16* __restrict__ Ahi,
                     const __nv_bfloat16* __restrict__ Alo,
                     const __nv_bfloat16* __restrict__ Bhi,
                     const __nv_bfloat16* __restrict__ Blo,
                     float* __restrict__ C, int M, int N, int K) {
    extern __shared__ char sm[];
    const uint32_t sb = smem_u32(sm);
    const int tid = threadIdx.x;
    const int wid = tid >> 5;
    const int lane = tid & 31;
    const int warp_m = wid & 3;
    const int warp_n = wid >> 2;
    const int bm = blockIdx.y * 128;
    const int bn = blockIdx.x * 128;

    // loader: row = tid>>2 (+64 second pass), 16B chunk = tid&3
    const int lrow = tid >> 2;
    const int lce  = (tid & 3) * 8;           // element offset within row
    const uint32_t so = (uint32_t)lrow * GS_STRIDE + (uint32_t)(tid & 3) * 16;

    // ldmatrix base addresses (k16 step s adds s*32 bytes)
    const int lr = lane & 7;
    const int quad = lane >> 3;
    // A: quad0: m0+lr,k0 | quad1: m0+8+lr,k0 | quad2: m0+lr,+16B | quad3: m0+8+lr,+16B
    const uint32_t a_off = (uint32_t)(warp_m * 32 + lr + (quad & 1) * 8) * GS_STRIDE
                         + (uint32_t)(quad >> 1) * 16;
    // B: quad0: n0+lr,k0 | quad1: n0+lr,+16B | quad2: n0+8+lr,k0 | quad3: n0+8+lr,+16B
    const uint32_t b_off = (uint32_t)(warp_n * 64 + lr + (quad >> 1) * 8) * GS_STRIDE
                         + (uint32_t)(quad & 1) * 16;

    float acc[2][8][4];
    #pragma unroll
    for (int mt = 0; mt < 2; mt++)
        #pragma unroll
        for (int nt = 0; nt < 8; nt++)
            #pragma unroll
            for (int r = 0; r < 4; r++) acc[mt][nt][r] = 0.0f;

    for (int k0 = 0; k0 < K; k0 += 32) {
        __syncthreads();
        #pragma unroll
        for (int p = 0; p < 2; p++) {
            int row = lrow + p * 64;
            size_t ga = (size_t)(bm + row) * K + k0 + lce;
            size_t gb = (size_t)(bn + row) * K + k0 + lce;
            uint32_t s2 = so + (uint32_t)(p * 64 * GS_STRIDE);
            *(uint4*)(sm + GS_AHI + s2) = *(const uint4*)(Ahi + ga);
            *(uint4*)(sm + GS_ALO + s2) = *(const uint4*)(Alo + ga);
            *(uint4*)(sm + GS_BHI + s2) = *(const uint4*)(Bhi + gb);
            *(uint4*)(sm + GS_BLO + s2) = *(const uint4*)(Blo + gb);
        }
        __syncthreads();

        #pragma unroll
        for (int s = 0; s < 2; s++) {          // two k16 steps in BK=32
            const uint32_t ks = (uint32_t)s * 32;
            uint32_t afh[2][4], afl[2][4];
            #pragma unroll
            for (int mt = 0; mt < 2; mt++) {
                uint32_t ao = a_off + (uint32_t)(mt * 16) * GS_STRIDE + ks;
                ldsm_x4(afh[mt], sb + GS_AHI + ao);
                ldsm_x4(afl[mt], sb + GS_ALO + ao);
            }
            #pragma unroll
            for (int np = 0; np < 4; np++) {   // pairs of n8 tiles
                uint32_t bo = b_off + (uint32_t)(np * 16) * GS_STRIDE + ks;
                uint32_t bfh[4], bfl[4];
                ldsm_x4(bfh, sb + GS_BHI + bo);
                ldsm_x4(bfl, sb + GS_BLO + bo);
                #pragma unroll
                for (int mt = 0; mt < 2; mt++) {
                    mma16816(acc[mt][2 * np],     afh[mt], bfh);
                    mma16816(acc[mt][2 * np + 1], afh[mt], bfh + 2);
                    mma16816(acc[mt][2 * np],     afh[mt], bfl);
                    mma16816(acc[mt][2 * np + 1], afh[mt], bfl + 2);
                    mma16816(acc[mt][2 * np],     afl[mt], bfh);
                    mma16816(acc[mt][2 * np + 1], afl[mt], bfh + 2);
                }
            }
        }
    }

    // epilogue
    #pragma unroll
    for (int mt = 0; mt < 2; mt++) {
        int row = bm + warp_m * 32 + mt * 16 + (lane >> 2);
        #pragma unroll
        for (int nt = 0; nt < 8; nt++) {
            int col = bn + warp_n * 64 + nt * 8 + (lane & 3) * 2;
            *(float2*)(C + (size_t)row * N + col) =
                make_float2(acc[mt][nt][0], acc[mt][nt][1]);
            *(float2*)(C + (size_t)(row + 8) * N + col) =
                make_float2(acc[mt][nt][2], acc[mt][nt][3]);
        }
    }
}

// ---------------- Flash attention v3 (causal, fp32, FFMA2, 512 thr) ----------
// grid: (T/128, B*H). block: 512 threads. BM=128, BN=64, microtile 4x4.
__global__ __launch_bounds__(512, 1) void flash_kernel(
    const float* __restrict__ qkv, float* __restrict__ yout)
{
    extern __shared__ float smf[];
    float* Qs = smf;                 // [128][68]
    float* Ks = Qs + 128 * 68;       // [64][64] granule-swizzled
    float* Vs = Ks + 64 * 64;        // [64][68]
    float* Ps = Vs + 64 * 68;        // [128][68]

    const int tid = threadIdx.x;
    const int tx = tid & 15;         // col group (4 cols)
    const int ty = tid >> 4;         // row group (4 rows), 0..31
    const int bq = (gridDim.x - 1) - blockIdx.x;   // heavy blocks first
    const int b  = blockIdx.y >> 4;
    const int h  = blockIdx.y & 15;

    const float* base = qkv + (size_t)b * TT * QKVN + h * DD;
    const int qrow0 = bq * 128;

    const int ln  = tid >> 4;        // 0..31 (row within pass)
    const int lg  = tid & 15;        // 16B granule
    const int ld4 = lg * 4;

    #pragma unroll
    for (int r = 0; r < 4; r++) {
        int n = ln + r * 32;
        *(float4*)(Qs + n * 68 + ld4) =
            *(const float4*)(base + (size_t)(qrow0 + n) * QKVN + ld4);
    }

    ull   O2[4][4];
    float m[4], l[4];
    #pragma unroll
    for (int i = 0; i < 4; i++) {
        m[i] = -1e30f; l[i] = 0.0f;
        #pragma unroll
        for (int jj = 0; jj < 4; jj++) O2[i][jj] = 0ull;
    }

    const int jmax = 2 * bq + 1;
    for (int j = 0; j <= jmax; j++) {
        __syncthreads();
        #pragma unroll
        for (int r = 0; r < 2; r++) {
            int n = ln + r * 32;
            const float* kp = base + EE     + (size_t)(j * 64 + n) * QKVN + ld4;
            const float* vp = base + 2 * EE + (size_t)(j * 64 + n) * QKVN + ld4;
            int gp = (lg ^ (n >> 2)) & 15;
            *(float4*)(Ks + n * 64 + gp * 4) = *(const float4*)kp;
            *(float4*)(Vs + n * 68 + ld4)    = *(const float4*)vp;
        }
        __syncthreads();

        // ---- S = Q @ K^T, packed over k-parity ----
        ull s2[4][4];
        #pragma unroll
        for (int i = 0; i < 4; i++)
            #pragma unroll
            for (int jj = 0; jj < 4; jj++) s2[i][jj] = 0ull;

        #pragma unroll 2
        for (int kk4 = 0; kk4 < 16; kk4++) {
            const int kk = kk4 * 4;
            const int gp = ((kk4 ^ tx) & 15) * 4;
            float4 k4[4];
            #pragma unroll
            for (int jj = 0; jj < 4; jj++)
                k4[jj] = *(const float4*)(Ks + (4 * tx + jj) * 64 + gp);
            #pragma unroll
            for (int i = 0; i < 4; i++) {
                float4 q4 = *(const float4*)(Qs + (ty * 4 + i) * 68 + kk);
                ull axy = pk2(q4.x, q4.y), azw = pk2(q4.z, q4.w);
                #pragma unroll
                for (int jj = 0; jj < 4; jj++) {
                    s2[i][jj] = ffma2(axy, pk2(k4[jj].x, k4[jj].y), s2[i][jj]);
                    s2[i][jj] = ffma2(azw, pk2(k4[jj].z, k4[jj].w), s2[i][jj]);
                }
            }
        }

        // ---- online softmax (row owned by 16-lane half-warp) ----
        const bool diag = (j * 64 + 63) > qrow0;
        #pragma unroll
        for (int i = 0; i < 4; i++) {
            float sv[4];
            #pragma unroll
            for (int jj = 0; jj < 4; jj++) {
                float lo, hi; upk2(s2[i][jj], lo, hi);
                sv[jj] = (lo + hi) * 0.125f;
            }
            if (diag) {
                int qr = qrow0 + ty * 4 + i;
                int kc = j * 64 + tx * 4;
                #pragma unroll
                for (int jj = 0; jj < 4; jj++)
                    if (kc + jj > qr) sv[jj] = -1e30f;
            }
            float rmax = fmaxf(fmaxf(sv[0], sv[1]), fmaxf(sv[2], sv[3]));
            #pragma unroll
            for (int off = 8; off >= 1; off >>= 1)
                rmax = fmaxf(rmax, __shfl_xor_sync(0xffffffffu, rmax, off));
            float mnew  = fmaxf(m[i], rmax);
            float alpha = __expf(m[i] - mnew);
            float p0 = __expf(sv[0] - mnew);
            float p1 = __expf(sv[1] - mnew);
            float p2 = __expf(sv[2] - mnew);
            float p3 = __expf(sv[3] - mnew);
            float rsum = p0 + p1 + p2 + p3;
            #pragma unroll
            for (int off = 8; off >= 1; off >>= 1)
                rsum += __shfl_xor_sync(0xffffffffu, rsum, off);
            l[i] = l[i] * alpha + rsum;
            m[i] = mnew;
            *(float4*)(Ps + (ty * 4 + i) * 68 + tx * 4) = make_float4(p0, p1, p2, p3);
            ull a2 = pk2(alpha, alpha);
            #pragma unroll
            for (int jj = 0; jj < 4; jj++) O2[i][jj] = fmul2(O2[i][jj], a2);
        }
        __syncthreads();

        // ---- O += P @ V, packed over k-parity ----
        #pragma unroll 2
        for (int kk = 0; kk < 64; kk += 4) {
            float4 v0 = *(const float4*)(Vs + (kk + 0) * 68 + 4 * tx);
            float4 v1 = *(const float4*)(Vs + (kk + 1) * 68 + 4 * tx);
            float4 v2 = *(const float4*)(Vs + (kk + 2) * 68 + 4 * tx);
            float4 v3 = *(const float4*)(Vs + (kk + 3) * 68 + 4 * tx);
            ull b01[4] = { pk2(v0.x, v1.x), pk2(v0.y, v1.y),
                           pk2(v0.z, v1.z), pk2(v0.w, v1.w) };
            ull b23[4] = { pk2(v2.x, v3.x), pk2(v2.y, v3.y),
                           pk2(v2.z, v3.z), pk2(v2.w, v3.w) };
            #pragma unroll
            for (int i = 0; i < 4; i++) {
                float4 p4 = *(const float4*)(Ps + (ty * 4 + i) * 68 + kk);
                ull pa = pk2(p4.x, p4.y), pb = pk2(p4.z, p4.w);
                #pragma unroll
                for (int jj = 0; jj < 4; jj++) {
                    O2[i][jj] = ffma2(pa, b01[jj], O2[i][jj]);
                    O2[i][jj] = ffma2(pb, b23[jj], O2[i][jj]);
                }
            }
        }
    }

    #pragma unroll
    for (int i = 0; i < 4; i++) {
        float inv = 1.0f / l[i];
        int row = b * TT + qrow0 + ty * 4 + i;
        float o[4];
        #pragma unroll
        for (int jj = 0; jj < 4; jj++) {
            float lo, hi; upk2(O2[i][jj], lo, hi);
            o[jj] = (lo + hi) * inv;
        }
        *(float4*)(yout + (size_t)row * EE + h * DD + tx * 4) =
            make_float4(o[0], o[1], o[2], o[3]);
    }
}

// ---------------- Memory attention (top-3) + gated fusion ----------------
// One warp per (b, t, h). Lane owns 2 of the 64 head dims.
// Emits combined in split-bf16 (hi/lo) directly for the proj GEMM.
__global__ __launch_bounds__(256) void memgate_kernel(
    const float* __restrict__ qkv, const float* __restrict__ mem_k,
    const float* __restrict__ mem_v, const float* __restrict__ gate_bias,
    const float* __restrict__ yin,
    __nv_bfloat16* __restrict__ chi, __nv_bfloat16* __restrict__ clo)
{
    const int gw   = (blockIdx.x * blockDim.x + threadIdx.x) >> 5;
    const int lane = threadIdx.x & 31;
    const int h  = gw & (HH - 1);
    const int bt = gw >> 4;            // 0..8191

    const size_t col = (size_t)h * DD + lane * 2;
    const float* qp = qkv + (size_t)bt * QKVN + col;
    const float q0 = qp[0], q1 = qp[1];

    const float* mkb = mem_k + (size_t)bt * KTOP * EE + col;
    const float* mvb = mem_v + (size_t)bt * KTOP * EE + col;

    float s[KTOP];
    #pragma unroll
    for (int k = 0; k < KTOP; k++) {
        float2 mk = *(const float2*)(mkb + (size_t)k * EE);
        float p = q0 * mk.x + q1 * mk.y;
        #pragma unroll
        for (int off = 16; off >= 1; off >>= 1)
            p += __shfl_xor_sync(0xffffffffu, p, off);
        s[k] = p * 4096.0f;            // mem_scale = E * sqrt(H)
    }

    float mx = fmaxf(s[0], fmaxf(s[1], s[2]));
    float e0 = __expf(s[0] - mx);
    float e1 = __expf(s[1] - mx);
    float e2 = __expf(s[2] - mx);
    float inv = 1.0f / (e0 + e1 + e2);

    float2 mv0 = *(const float2*)(mvb + 0 * EE);
    float2 mv1 = *(const float2*)(mvb + 1 * EE);
    float2 mv2 = *(const float2*)(mvb + 2 * EE);
    float w0 = e0 * inv, w1 = e1 * inv, w2 = e2 * inv;
    float a0 = w0 * mv0.x + w1 * mv1.x + w2 * mv2.x;
    float a1 = w0 * mv0.y + w1 * mv1.y + w2 * mv2.y;

    const float g = gate_bias[h];
    const size_t yi = (size_t)bt * EE + col;
    float2 yv = *(const float2*)(yin + yi);
    float o0 = a0 * g + yv.x * (1.0f - g);
    float o1 = a1 * g + yv.y * (1.0f - g);

    __nv_bfloat16 h0 = __float2bfloat16(o0);
    __nv_bfloat16 h1 = __float2bfloat16(o1);
    *(__nv_bfloat162*)(chi + yi) = __halves2bfloat162(h0, h1);
    *(__nv_bfloat162*)(clo + yi) =
        __halves2bfloat162(__float2bfloat16(o0 - __bfloat162float(h0)),
                           __float2bfloat16(o1 - __bfloat162float(h1)));
}

// ---------------- launch ----------------
extern "C" void kernel_launch(void* const* d_in, const int* in_sizes, int n_in,
                              void* d_out, int out_size)
{
    (void)in_sizes; (void)n_in; (void)out_size;
    const float* x         = (const float*)d_in[0];
    const float* mem_k     = (const float*)d_in[1];
    const float* mem_v     = (const float*)d_in[2];
    const float* W_attn    = (const float*)d_in[3];
    const float* W_proj    = (const float*)d_in[4];
    const float* gate_bias = (const float*)d_in[5];
    float* out = (float*)d_out;

    float *qkv, *ybuf;
    __nv_bfloat16 *xhi, *xlo, *wahi, *walo, *wphi, *wplo, *chi, *clo;
    cudaGetSymbolAddress((void**)&qkv,  g_qkv);
    cudaGetSymbolAddress((void**)&ybuf, g_y);
    cudaGetSymbolAddress((void**)&xhi,  g_xhi);
    cudaGetSymbolAddress((void**)&xlo,  g_xlo);
    cudaGetSymbolAddress((void**)&wahi, g_wahi);
    cudaGetSymbolAddress((void**)&walo, g_walo);
    cudaGetSymbolAddress((void**)&wphi, g_wphi);
    cudaGetSymbolAddress((void**)&wplo, g_wplo);
    cudaGetSymbolAddress((void**)&chi,  g_chi);
    cudaGetSymbolAddress((void**)&clo,  g_clo);

    // 0) split-convert x; transpose+split weights
    {
        int n4 = (MROWS * EE) / 4;
        convert_split_kernel<<<(n4 + 255) / 256, 256>>>((const float4*)x, xhi, xlo, n4);
        dim3 tb(32, 8);
        transpose_split_kernel<<<dim3(QKVN / 32, EE / 32), tb>>>(W_attn, wahi, walo, EE, QKVN);
        transpose_split_kernel<<<dim3(EE / 32, EE / 32), tb>>>(W_proj, wphi, wplo, EE, EE);
    }

    // 1) qkv = x @ W_attn (mma.sync split-bf16)
    {
        cudaFuncSetAttribute(gemm_mma_kernel,
                             cudaFuncAttributeMaxDynamicSharedMemorySize, GS_TOTAL);
        gemm_mma_kernel<<<dim3(QKVN / 128, MROWS / 128), 256, GS_TOTAL>>>(
            xhi, xlo, wahi, walo, qkv, MROWS, QKVN, EE);
    }

    // 2) causal flash attention -> g_y
    {
        const int smem = (128 * 68 + 64 * 64 + 64 * 68 + 128 * 68) * 4; // 103424 B
        cudaFuncSetAttribute(flash_kernel,
                             cudaFuncAttributeMaxDynamicSharedMemorySize, smem);
        flash_kernel<<<dim3(TT / 128, BB * HH), 512, smem>>>(qkv, ybuf);
    }

    // 3) memory attention + gated fusion -> split-bf16 combined
    {
        const int nwarp = BB * TT * HH;
        memgate_kernel<<<nwarp / 8, 256>>>(qkv, mem_k, mem_v, gate_bias, ybuf, chi, clo);
    }

    // 4) out = combined @ W_proj (mma.sync split-bf16)
    {
        gemm_mma_kernel<<<dim3(EE / 128, MROWS / 128), 256, GS_TOTAL>>>(
            chi, clo, wphi, wplo, out, MROWS, EE, EE);
    }
}

// round 16
// speedup vs baseline: 1.5986x; 1.5986x over previous
#include <cuda_runtime.h>
#include <cuda_bf16.h>
#include <cstdint>

// Problem dims (fixed by the dataset)
#define BB    4
#define TT    2048
#define EE    1024
#define HH    16
#define DD    64
#define KTOP  3
#define MROWS (BB * TT)      // 8192
#define QKVN  (3 * EE)       // 3072

typedef unsigned long long ull;

// ---------------- scratch (allocation-free rule: __device__ globals) ---------
__device__ float g_qkv[(size_t)MROWS * QKVN];           // 96 MB fp32
__device__ float g_y[(size_t)MROWS * EE];               // 32 MB fp32
__device__ __nv_bfloat16 g_xhi[(size_t)MROWS * EE];
__device__ __nv_bfloat16 g_xlo[(size_t)MROWS * EE];
__device__ __nv_bfloat16 g_wahi[(size_t)QKVN * EE];     // W_attn^T [3072,1024]
__device__ __nv_bfloat16 g_walo[(size_t)QKVN * EE];
__device__ __nv_bfloat16 g_wphi[(size_t)EE * EE];       // W_proj^T [1024,1024]
__device__ __nv_bfloat16 g_wplo[(size_t)EE * EE];
__device__ __nv_bfloat16 g_chi[(size_t)MROWS * EE];     // combined hi/lo
__device__ __nv_bfloat16 g_clo[(size_t)MROWS * EE];

// ---------------- helpers ----------------
__device__ __forceinline__ uint32_t smem_u32(const void* p) {
    uint32_t a;
    asm("{ .reg .u64 t; cvta.to.shared.u64 t, %1; cvt.u32.u64 %0, t; }"
        : "=r"(a) : "l"(p));
    return a;
}
__device__ __forceinline__ void ldsm_x4(uint32_t* r, uint32_t addr) {
    asm volatile("ldmatrix.sync.aligned.m8n8.x4.shared.b16 {%0,%1,%2,%3}, [%4];"
                 : "=r"(r[0]), "=r"(r[1]), "=r"(r[2]), "=r"(r[3]) : "r"(addr));
}
__device__ __forceinline__ void mma16816(float* d, const uint32_t* a,
                                         const uint32_t* b) {
    asm volatile("mma.sync.aligned.m16n8k16.row.col.f32.bf16.bf16.f32 "
                 "{%0,%1,%2,%3}, {%4,%5,%6,%7}, {%8,%9}, {%0,%1,%2,%3};"
                 : "+f"(d[0]), "+f"(d[1]), "+f"(d[2]), "+f"(d[3])
                 : "r"(a[0]), "r"(a[1]), "r"(a[2]), "r"(a[3]),
                   "r"(b[0]), "r"(b[1]));
}

// ---------------- packed f32x2 helpers (Blackwell FFMA2) ----------------
__device__ __forceinline__ ull pk2(float x, float y) {
    ull r; asm("mov.b64 %0, {%1, %2};" : "=l"(r) : "f"(x), "f"(y)); return r;
}
__device__ __forceinline__ void upk2(ull v, float &x, float &y) {
    asm("mov.b64 {%0, %1}, %2;" : "=f"(x), "=f"(y) : "l"(v));
}
__device__ __forceinline__ ull ffma2(ull a, ull b, ull c) {
    ull d; asm("fma.rn.f32x2 %0, %1, %2, %3;" : "=l"(d) : "l"(a), "l"(b), "l"(c)); return d;
}
__device__ __forceinline__ ull fmul2(ull a, ull b) {
    ull d; asm("mul.rn.f32x2 %0, %1, %2;" : "=l"(d) : "l"(a), "l"(b)); return d;
}

// ============ pre-kernels: split-convert and transpose-split ============
__global__ void convert_split_kernel(const float4* __restrict__ src,
                                     __nv_bfloat16* __restrict__ hi,
                                     __nv_bfloat16* __restrict__ lo, int n4) {
    int i = blockIdx.x * blockDim.x + threadIdx.x;
    if (i >= n4) return;
    float4 v = src[i];
    __nv_bfloat16 h0 = __float2bfloat16(v.x), h1 = __float2bfloat16(v.y);
    __nv_bfloat16 h2 = __float2bfloat16(v.z), h3 = __float2bfloat16(v.w);
    __nv_bfloat162* H = (__nv_bfloat162*)(hi + (size_t)i * 4);
    H[0] = __halves2bfloat162(h0, h1);
    H[1] = __halves2bfloat162(h2, h3);
    __nv_bfloat162* L = (__nv_bfloat162*)(lo + (size_t)i * 4);
    L[0] = __halves2bfloat162(__float2bfloat16(v.x - __bfloat162float(h0)),
                              __float2bfloat16(v.y - __bfloat162float(h1)));
    L[1] = __halves2bfloat162(__float2bfloat16(v.z - __bfloat162float(h2)),
                              __float2bfloat16(v.w - __bfloat162float(h3)));
}

// W [K,N] row-major -> Wt [N,K] split into bf16 hi/lo
__global__ void transpose_split_kernel(const float* __restrict__ W,
                                       __nv_bfloat16* __restrict__ Thi,
                                       __nv_bfloat16* __restrict__ Tlo,
                                       int K, int N) {
    __shared__ float t[32][33];
    int n0 = blockIdx.x * 32, k0 = blockIdx.y * 32;
    int tx = threadIdx.x, ty = threadIdx.y;
    #pragma unroll
    for (int r = 0; r < 32; r += 8)
        t[ty + r][tx] = W[(size_t)(k0 + ty + r) * N + n0 + tx];
    __syncthreads();
    #pragma unroll
    for (int r = 0; r < 32; r += 8) {
        float v = t[tx][ty + r];
        __nv_bfloat16 h = __float2bfloat16(v);
        size_t o = (size_t)(n0 + ty + r) * K + k0 + tx;
        Thi[o] = h;
        Tlo[o] = __float2bfloat16(v - __bfloat162float(h));
    }
}

// ============ mma.sync split-bf16 GEMM ============
// C[M,N] = A[M,K] @ Bt[N,K]^T, fp32 out. BM=BN=128, BK=32, 256 thr, 8 warps.
// Warp grid 4(m) x 2(n); warp tile 32x64; m16n8k16 HMMA; pad-80B smem rows.
#define GS_STRIDE 80
#define GS_AHI 0
#define GS_ALO (128 * GS_STRIDE)
#define GS_BHI (2 * 128 * GS_STRIDE)
#define GS_BLO (3 * 128 * GS_STRIDE)
#define GS_TOTAL (4 * 128 * GS_STRIDE)   // 40960 B

__global__ __launch_bounds__(256, 2)
void gemm_mma_kernel(const __nv_bfloat16* __restrict__ Ahi,
                     const __nv_bfloat16* __restrict__ Alo,
                     const __nv_bfloat16* __restrict__ Bhi,
                     const __nv_bfloat16* __restrict__ Blo,
                     float* __restrict__ C, int M, int N, int K) {
    extern __shared__ char sm[];
    const uint32_t sb = smem_u32(sm);
    const int tid = threadIdx.x;
    const int wid = tid >> 5;
    const int lane = tid & 31;
    const int warp_m = wid & 3;
    const int warp_n = wid >> 2;
    const int bm = blockIdx.y * 128;
    const int bn = blockIdx.x * 128;

    // loader: row = tid>>2 (+64 second pass), 16B chunk = tid&3
    const int lrow = tid >> 2;
    const int lce  = (tid & 3) * 8;           // element offset within row
    const uint32_t so = (uint32_t)lrow * GS_STRIDE + (uint32_t)(tid & 3) * 16;

    // ldmatrix base addresses (k16 step s adds s*32 bytes)
    const int lr = lane & 7;
    const int quad = lane >> 3;
    // A: quad0: m0+lr,k0 | quad1: m0+8+lr,k0 | quad2: m0+lr,+16B | quad3: m0+8+lr,+16B
    const uint32_t a_off = (uint32_t)(warp_m * 32 + lr + (quad & 1) * 8) * GS_STRIDE
                         + (uint32_t)(quad >> 1) * 16;
    // B: quad0: n0+lr,k0 | quad1: n0+lr,+16B | quad2: n0+8+lr,k0 | quad3: n0+8+lr,+16B
    const uint32_t b_off = (uint32_t)(warp_n * 64 + lr + (quad >> 1) * 8) * GS_STRIDE
                         + (uint32_t)(quad & 1) * 16;

    float acc[2][8][4];
    #pragma unroll
    for (int mt = 0; mt < 2; mt++)
        #pragma unroll
        for (int nt = 0; nt < 8; nt++)
            #pragma unroll
            for (int r = 0; r < 4; r++) acc[mt][nt][r] = 0.0f;

    for (int k0 = 0; k0 < K; k0 += 32) {
        __syncthreads();
        #pragma unroll
        for (int p = 0; p < 2; p++) {
            int row = lrow + p * 64;
            size_t ga = (size_t)(bm + row) * K + k0 + lce;
            size_t gb = (size_t)(bn + row) * K + k0 + lce;
            uint32_t s2 = so + (uint32_t)(p * 64 * GS_STRIDE);
            *(uint4*)(sm + GS_AHI + s2) = *(const uint4*)(Ahi + ga);
            *(uint4*)(sm + GS_ALO + s2) = *(const uint4*)(Alo + ga);
            *(uint4*)(sm + GS_BHI + s2) = *(const uint4*)(Bhi + gb);
            *(uint4*)(sm + GS_BLO + s2) = *(const uint4*)(Blo + gb);
        }
        __syncthreads();

        #pragma unroll
        for (int s = 0; s < 2; s++) {          // two k16 steps in BK=32
            const uint32_t ks = (uint32_t)s * 32;
            uint32_t afh[2][4], afl[2][4];
            #pragma unroll
            for (int mt = 0; mt < 2; mt++) {
                uint32_t ao = a_off + (uint32_t)(mt * 16) * GS_STRIDE + ks;
                ldsm_x4(afh[mt], sb + GS_AHI + ao);
                ldsm_x4(afl[mt], sb + GS_ALO + ao);
            }
            #pragma unroll
            for (int np = 0; np < 4; np++) {   // pairs of n8 tiles
                uint32_t bo = b_off + (uint32_t)(np * 16) * GS_STRIDE + ks;
                uint32_t bfh[4], bfl[4];
                ldsm_x4(bfh, sb + GS_BHI + bo);
                ldsm_x4(bfl, sb + GS_BLO + bo);
                #pragma unroll
                for (int mt = 0; mt < 2; mt++) {
                    mma16816(acc[mt][2 * np],     afh[mt], bfh);
                    mma16816(acc[mt][2 * np + 1], afh[mt], bfh + 2);
                    mma16816(acc[mt][2 * np],     afh[mt], bfl);
                    mma16816(acc[mt][2 * np + 1], afh[mt], bfl + 2);
                    mma16816(acc[mt][2 * np],     afl[mt], bfh);
                    mma16816(acc[mt][2 * np + 1], afl[mt], bfh + 2);
                }
            }
        }
    }

    // epilogue
    #pragma unroll
    for (int mt = 0; mt < 2; mt++) {
        int row = bm + warp_m * 32 + mt * 16 + (lane >> 2);
        #pragma unroll
        for (int nt = 0; nt < 8; nt++) {
            int col = bn + warp_n * 64 + nt * 8 + (lane & 3) * 2;
            *(float2*)(C + (size_t)row * N + col) =
                make_float2(acc[mt][nt][0], acc[mt][nt][1]);
            *(float2*)(C + (size_t)(row + 8) * N + col) =
                make_float2(acc[mt][nt][2], acc[mt][nt][3]);
        }
    }
}

// ---------------- Flash attention v3 (causal, fp32, FFMA2, 512 thr) ----------
// grid: (T/128, B*H). block: 512 threads. BM=128, BN=64, microtile 4x4.
__global__ __launch_bounds__(512, 1) void flash_kernel(
    const float* __restrict__ qkv, float* __restrict__ yout)
{
    extern __shared__ float smf[];
    float* Qs = smf;                 // [128][68]
    float* Ks = Qs + 128 * 68;       // [64][64] granule-swizzled
    float* Vs = Ks + 64 * 64;        // [64][68]
    float* Ps = Vs + 64 * 68;        // [128][68]

    const int tid = threadIdx.x;
    const int tx = tid & 15;         // col group (4 cols)
    const int ty = tid >> 4;         // row group (4 rows), 0..31
    const int bq = (gridDim.x - 1) - blockIdx.x;   // heavy blocks first
    const int b  = blockIdx.y >> 4;
    const int h  = blockIdx.y & 15;

    const float* base = qkv + (size_t)b * TT * QKVN + h * DD;
    const int qrow0 = bq * 128;

    const int ln  = tid >> 4;        // 0..31 (row within pass)
    const int lg  = tid & 15;        // 16B granule
    const int ld4 = lg * 4;

    #pragma unroll
    for (int r = 0; r < 4; r++) {
        int n = ln + r * 32;
        *(float4*)(Qs + n * 68 + ld4) =
            *(const float4*)(base + (size_t)(qrow0 + n) * QKVN + ld4);
    }

    ull   O2[4][4];
    float m[4], l[4];
    #pragma unroll
    for (int i = 0; i < 4; i++) {
        m[i] = -1e30f; l[i] = 0.0f;
        #pragma unroll
        for (int jj = 0; jj < 4; jj++) O2[i][jj] = 0ull;
    }

    const int jmax = 2 * bq + 1;
    for (int j = 0; j <= jmax; j++) {
        __syncthreads();
        #pragma unroll
        for (int r = 0; r < 2; r++) {
            int n = ln + r * 32;
            const float* kp = base + EE     + (size_t)(j * 64 + n) * QKVN + ld4;
            const float* vp = base + 2 * EE + (size_t)(j * 64 + n) * QKVN + ld4;
            int gp = (lg ^ (n >> 2)) & 15;
            *(float4*)(Ks + n * 64 + gp * 4) = *(const float4*)kp;
            *(float4*)(Vs + n * 68 + ld4)    = *(const float4*)vp;
        }
        __syncthreads();

        // ---- S = Q @ K^T, packed over k-parity ----
        ull s2[4][4];
        #pragma unroll
        for (int i = 0; i < 4; i++)
            #pragma unroll
            for (int jj = 0; jj < 4; jj++) s2[i][jj] = 0ull;

        #pragma unroll 2
        for (int kk4 = 0; kk4 < 16; kk4++) {
            const int kk = kk4 * 4;
            const int gp = ((kk4 ^ tx) & 15) * 4;
            float4 k4[4];
            #pragma unroll
            for (int jj = 0; jj < 4; jj++)
                k4[jj] = *(const float4*)(Ks + (4 * tx + jj) * 64 + gp);
            #pragma unroll
            for (int i = 0; i < 4; i++) {
                float4 q4 = *(const float4*)(Qs + (ty * 4 + i) * 68 + kk);
                ull axy = pk2(q4.x, q4.y), azw = pk2(q4.z, q4.w);
                #pragma unroll
                for (int jj = 0; jj < 4; jj++) {
                    s2[i][jj] = ffma2(axy, pk2(k4[jj].x, k4[jj].y), s2[i][jj]);
                    s2[i][jj] = ffma2(azw, pk2(k4[jj].z, k4[jj].w), s2[i][jj]);
                }
            }
        }

        // ---- online softmax (row owned by 16-lane half-warp) ----
        const bool diag = (j * 64 + 63) > qrow0;
        #pragma unroll
        for (int i = 0; i < 4; i++) {
            float sv[4];
            #pragma unroll
            for (int jj = 0; jj < 4; jj++) {
                float lo, hi; upk2(s2[i][jj], lo, hi);
                sv[jj] = (lo + hi) * 0.125f;
            }
            if (diag) {
                int qr = qrow0 + ty * 4 + i;
                int kc = j * 64 + tx * 4;
                #pragma unroll
                for (int jj = 0; jj < 4; jj++)
                    if (kc + jj > qr) sv[jj] = -1e30f;
            }
            float rmax = fmaxf(fmaxf(sv[0], sv[1]), fmaxf(sv[2], sv[3]));
            #pragma unroll
            for (int off = 8; off >= 1; off >>= 1)
                rmax = fmaxf(rmax, __shfl_xor_sync(0xffffffffu, rmax, off));
            float mnew  = fmaxf(m[i], rmax);
            float alpha = __expf(m[i] - mnew);
            float p0 = __expf(sv[0] - mnew);
            float p1 = __expf(sv[1] - mnew);
            float p2 = __expf(sv[2] - mnew);
            float p3 = __expf(sv[3] - mnew);
            float rsum = p0 + p1 + p2 + p3;
            #pragma unroll
            for (int off = 8; off >= 1; off >>= 1)
                rsum += __shfl_xor_sync(0xffffffffu, rsum, off);
            l[i] = l[i] * alpha + rsum;
            m[i] = mnew;
            *(float4*)(Ps + (ty * 4 + i) * 68 + tx * 4) = make_float4(p0, p1, p2, p3);
            ull a2 = pk2(alpha, alpha);
            #pragma unroll
            for (int jj = 0; jj < 4; jj++) O2[i][jj] = fmul2(O2[i][jj], a2);
        }
        __syncthreads();

        // ---- O += P @ V, packed over k-parity ----
        #pragma unroll 2
        for (int kk = 0; kk < 64; kk += 4) {
            float4 v0 = *(const float4*)(Vs + (kk + 0) * 68 + 4 * tx);
            float4 v1 = *(const float4*)(Vs + (kk + 1) * 68 + 4 * tx);
            float4 v2 = *(const float4*)(Vs + (kk + 2) * 68 + 4 * tx);
            float4 v3 = *(const float4*)(Vs + (kk + 3) * 68 + 4 * tx);
            ull b01[4] = { pk2(v0.x, v1.x), pk2(v0.y, v1.y),
                           pk2(v0.z, v1.z), pk2(v0.w, v1.w) };
            ull b23[4] = { pk2(v2.x, v3.x), pk2(v2.y, v3.y),
                           pk2(v2.z, v3.z), pk2(v2.w, v3.w) };
            #pragma unroll
            for (int i = 0; i < 4; i++) {
                float4 p4 = *(const float4*)(Ps + (ty * 4 + i) * 68 + kk);
                ull pa = pk2(p4.x, p4.y), pb = pk2(p4.z, p4.w);
                #pragma unroll
                for (int jj = 0; jj < 4; jj++) {
                    O2[i][jj] = ffma2(pa, b01[jj], O2[i][jj]);
                    O2[i][jj] = ffma2(pb, b23[jj], O2[i][jj]);
                }
            }
        }
    }

    #pragma unroll
    for (int i = 0; i < 4; i++) {
        float inv = 1.0f / l[i];
        int row = b * TT + qrow0 + ty * 4 + i;
        float o[4];
        #pragma unroll
        for (int jj = 0; jj < 4; jj++) {
            float lo, hi; upk2(O2[i][jj], lo, hi);
            o[jj] = (lo + hi) * inv;
        }
        *(float4*)(yout + (size_t)row * EE + h * DD + tx * 4) =
            make_float4(o[0], o[1], o[2], o[3]);
    }
}

// ---------------- Memory attention (top-3) + gated fusion ----------------
// One warp per (b, t, h). Lane owns 2 of the 64 head dims.
// Emits combined in split-bf16 (hi/lo) directly for the proj GEMM.
__global__ __launch_bounds__(256) void memgate_kernel(
    const float* __restrict__ qkv, const float* __restrict__ mem_k,
    const float* __restrict__ mem_v, const float* __restrict__ gate_bias,
    const float* __restrict__ yin,
    __nv_bfloat16* __restrict__ chi, __nv_bfloat16* __restrict__ clo)
{
    const int gw   = (blockIdx.x * blockDim.x + threadIdx.x) >> 5;
    const int lane = threadIdx.x & 31;
    const int h  = gw & (HH - 1);
    const int bt = gw >> 4;            // 0..8191

    const size_t col = (size_t)h * DD + lane * 2;
    const float* qp = qkv + (size_t)bt * QKVN + col;
    const float q0 = qp[0], q1 = qp[1];

    const float* mkb = mem_k + (size_t)bt * KTOP * EE + col;
    const float* mvb = mem_v + (size_t)bt * KTOP * EE + col;

    float s[KTOP];
    #pragma unroll
    for (int k = 0; k < KTOP; k++) {
        float2 mk = *(const float2*)(mkb + (size_t)k * EE);
        float p = q0 * mk.x + q1 * mk.y;
        #pragma unroll
        for (int off = 16; off >= 1; off >>= 1)
            p += __shfl_xor_sync(0xffffffffu, p, off);
        s[k] = p * 4096.0f;            // mem_scale = E * sqrt(H)
    }

    float mx = fmaxf(s[0], fmaxf(s[1], s[2]));
    float e0 = __expf(s[0] - mx);
    float e1 = __expf(s[1] - mx);
    float e2 = __expf(s[2] - mx);
    float inv = 1.0f / (e0 + e1 + e2);

    float2 mv0 = *(const float2*)(mvb + 0 * EE);
    float2 mv1 = *(const float2*)(mvb + 1 * EE);
    float2 mv2 = *(const float2*)(mvb + 2 * EE);
    float w0 = e0 * inv, w1 = e1 * inv, w2 = e2 * inv;
    float a0 = w0 * mv0.x + w1 * mv1.x + w2 * mv2.x;
    float a1 = w0 * mv0.y + w1 * mv1.y + w2 * mv2.y;

    const float g = gate_bias[h];
    const size_t yi = (size_t)bt * EE + col;
    float2 yv = *(const float2*)(yin + yi);
    float o0 = a0 * g + yv.x * (1.0f - g);
    float o1 = a1 * g + yv.y * (1.0f - g);

    __nv_bfloat16 h0 = __float2bfloat16(o0);
    __nv_bfloat16 h1 = __float2bfloat16(o1);
    *(__nv_bfloat162*)(chi + yi) = __halves2bfloat162(h0, h1);
    *(__nv_bfloat162*)(clo + yi) =
        __halves2bfloat162(__float2bfloat16(o0 - __bfloat162float(h0)),
                           __float2bfloat16(o1 - __bfloat162float(h1)));
}

// ---------------- launch ----------------
extern "C" void kernel_launch(void* const* d_in, const int* in_sizes, int n_in,
                              void* d_out, int out_size)
{
    (void)in_sizes; (void)n_in; (void)out_size;
    const float* x         = (const float*)d_in[0];
    const float* mem_k     = (const float*)d_in[1];
    const float* mem_v     = (const float*)d_in[2];
    const float* W_attn    = (const float*)d_in[3];
    const float* W_proj    = (const float*)d_in[4];
    const float* gate_bias = (const float*)d_in[5];
    float* out = (float*)d_out;

    float *qkv, *ybuf;
    __nv_bfloat16 *xhi, *xlo, *wahi, *walo, *wphi, *wplo, *chi, *clo;
    cudaGetSymbolAddress((void**)&qkv,  g_qkv);
    cudaGetSymbolAddress((void**)&ybuf, g_y);
    cudaGetSymbolAddress((void**)&xhi,  g_xhi);
    cudaGetSymbolAddress((void**)&xlo,  g_xlo);
    cudaGetSymbolAddress((void**)&wahi, g_wahi);
    cudaGetSymbolAddress((void**)&walo, g_walo);
    cudaGetSymbolAddress((void**)&wphi, g_wphi);
    cudaGetSymbolAddress((void**)&wplo, g_wplo);
    cudaGetSymbolAddress((void**)&chi,  g_chi);
    cudaGetSymbolAddress((void**)&clo,  g_clo);

    // 0) split-convert x; transpose+split weights
    {
        int n4 = (MROWS * EE) / 4;
        convert_split_kernel<<<(n4 + 255) / 256, 256>>>((const float4*)x, xhi, xlo, n4);
        dim3 tb(32, 8);
        transpose_split_kernel<<<dim3(QKVN / 32, EE / 32), tb>>>(W_attn, wahi, walo, EE, QKVN);
        transpose_split_kernel<<<dim3(EE / 32, EE / 32), tb>>>(W_proj, wphi, wplo, EE, EE);
    }

    // 1) qkv = x @ W_attn (mma.sync split-bf16)
    {
        cudaFuncSetAttribute(gemm_mma_kernel,
                             cudaFuncAttributeMaxDynamicSharedMemorySize, GS_TOTAL);
        gemm_mma_kernel<<<dim3(QKVN / 128, MROWS / 128), 256, GS_TOTAL>>>(
            xhi, xlo, wahi, walo, qkv, MROWS, QKVN, EE);
    }

    // 2) causal flash attention -> g_y
    {
        const int smem = (128 * 68 + 64 * 64 + 64 * 68 + 128 * 68) * 4; // 103424 B
        cudaFuncSetAttribute(flash_kernel,
                             cudaFuncAttributeMaxDynamicSharedMemorySize, smem);
        flash_kernel<<<dim3(TT / 128, BB * HH), 512, smem>>>(qkv, ybuf);
    }

    // 3) memory attention + gated fusion -> split-bf16 combined
    {
        const int nwarp = BB * TT * HH;
        memgate_kernel<<<nwarp / 8, 256>>>(qkv, mem_k, mem_v, gate_bias, ybuf, chi, clo);
    }

    // 4) out = combined @ W_proj (mma.sync split-bf16)
    {
        gemm_mma_kernel<<<dim3(EE / 128, MROWS / 128), 256, GS_TOTAL>>>(
            chi, clo, wphi, wplo, out, MROWS, EE, EE);
    }
}